// round 9
// baseline (speedup 1.0000x reference)
#include <cuda_runtime.h>
#include <cuda_fp16.h>
#include <float.h>
#include <math.h>
#include <stdint.h>

// ---------------- problem constants ----------------
#define T_TOK 8192
#define D_DIM 7168
#define E_EXP 256
#define N_GROUPS 8
#define TOPK_GROUPS 4
#define TOP_K 8

// ---------------- GEMM tiling ----------------
#define BM 128
#define BN 64
#define BK 32
#define NCHUNK (D_DIM / BK)      // 224
#define NTHREADS 512

// ---------------- smem layout ----------------
#define ASTR 48                          // bytes per 32-byte limb row (padded, ldsm conflict-free)
#define A_PL (128 * ASTR)                // 6144
#define B_PL (64 * ASTR)                 // 3072
#define RAW_STR 144                      // fp32 raw A row stride (128B data + pad)
#define RAW_PL (128 * RAW_STR)           // 18432
#define A_L(st, p) (((st) * 4 + (p)) * A_PL)            // [0, 49152)
#define B_L(st, p) (49152 + ((st) * 4 + (p)) * B_PL)    // [49152, 73728)
#define RAW_L(st)  (73728 + (st) * RAW_PL)              // [73728, 110592)
#define SMEM_BYTES 110592

// bucket scales: z = sum_b acc_b * 2^(-14-8b)
#define C0 6.103515625e-5f
#define C1 2.3841857910156250e-7f
#define C2 9.3132257461547852e-10f
#define C3 3.6379788070917130e-12f

// ---------------- device scratch ----------------
__device__ float g_scores[(size_t)T_TOK * E_EXP];             // sigmoid scores [T][E]
__device__ int8_t g_Wq[4][(size_t)E_EXP * D_DIM];             // W^T limbs [plane][E][D]

// ---------------- PTX helpers ----------------
__device__ __forceinline__ uint32_t smem_u32(const void* p) {
    uint32_t a;
    asm("{ .reg .u64 t; cvta.to.shared.u64 t, %1; cvt.u32.u64 %0, t; }" : "=r"(a) : "l"(p));
    return a;
}
__device__ __forceinline__ void imma(int* c, const uint32_t* a, const uint32_t* b) {
    asm volatile(
        "mma.sync.aligned.m16n8k32.row.col.s32.s8.s8.s32 "
        "{%0,%1,%2,%3}, {%4,%5,%6,%7}, {%8,%9}, {%0,%1,%2,%3};"
        : "+r"(c[0]), "+r"(c[1]), "+r"(c[2]), "+r"(c[3])
        : "r"(a[0]), "r"(a[1]), "r"(a[2]), "r"(a[3]), "r"(b[0]), "r"(b[1]));
}
__device__ __forceinline__ void ldsm4(uint32_t& r0, uint32_t& r1, uint32_t& r2, uint32_t& r3,
                                      uint32_t addr) {
    asm volatile("ldmatrix.sync.aligned.m8n8.x4.shared.b16 {%0,%1,%2,%3}, [%4];"
                 : "=r"(r0), "=r"(r1), "=r"(r2), "=r"(r3) : "r"(addr));
}
__device__ __forceinline__ void cpasync16(uint32_t saddr, const void* g) {
    asm volatile("cp.async.cg.shared.global [%0], [%1], 16;" :: "r"(saddr), "l"(g));
}
#define CP_COMMIT() asm volatile("cp.async.commit_group;" ::: "memory")
#define CP_WAIT(n)  asm volatile("cp.async.wait_group %0;" :: "n"(n) : "memory")

// balanced 4-limb s8 recode of round(f * 2^s): bytes [l3,l2,l1,l0] (l0 = most significant)
__device__ __forceinline__ uint32_t packA(float f) {
    int X = __float2int_rn(f * 268435456.0f);          // 2^28
    return ((uint32_t)(X + 0x00808080)) ^ 0x00808080u;
}

// ---------------------------------------------------------------------------
// W limb split + transpose: W[k][e] f32 -> g_Wq[p][e][k] s8 of round(w * 2^34)
// ---------------------------------------------------------------------------
__global__ __launch_bounds__(256) void wsplit_kernel(const float* __restrict__ W) {
    __shared__ float tile[32][33];
    const int k0 = blockIdx.x * 32, e0 = blockIdx.y * 32;
    const int tx = threadIdx.x, ty = threadIdx.y;   // 32 x 8
#pragma unroll
    for (int i = 0; i < 4; i++)
        tile[ty + 8 * i][tx] = W[(size_t)(k0 + ty + 8 * i) * E_EXP + e0 + tx];
    __syncthreads();

    const int kq = tx & 7, eg = tx >> 3;
    const int e = e0 + eg * 8 + ty;
    const int k = k0 + kq * 4;
    uint32_t w[4];
#pragma unroll
    for (int j = 0; j < 4; j++) {
        float f = tile[kq * 4 + j][eg * 8 + ty];
        int X = __float2int_rn(f * 17179869184.0f);    // 2^34
        w[j] = ((uint32_t)(X + 0x00808080)) ^ 0x00808080u;
    }
#pragma unroll
    for (int p = 0; p < 4; p++) {
        const uint32_t sel = (uint32_t)(3 - p) * 0x11u + 0x40u;
        uint32_t lo = __byte_perm(w[0], w[1], sel);
        uint32_t hi = __byte_perm(w[2], w[3], sel);
        uint32_t word = __byte_perm(lo, hi, 0x5410);
        *(uint32_t*)&g_Wq[p][(size_t)e * D_DIM + k] = word;
    }
}

// ---------------------------------------------------------------------------
// GEMM: scores = sigmoid(x @ W) via 4x4-limb s8 IMMA (10 pairs, fp32-exact).
// Grid (4, 64) = 256 CTAs. CTA 128x64, 512 threads, 16 warps 4(M)x4(N),
// warp tile 32x16.
// ---------------------------------------------------------------------------
__global__ __launch_bounds__(NTHREADS, 1) void gemm_imma_kernel(const float* __restrict__ x) {
    extern __shared__ char smc[];
    const uint32_t sb = smem_u32(smc);

    const int tid = threadIdx.x;
    const int lane = tid & 31, wid = tid >> 5;
    const int m0 = blockIdx.y * BM;
    const int n0 = blockIdx.x * BN;
    const int wm = (wid & 3) * 32;
    const int wn = (wid >> 2) * 16;
    const int g = lane >> 2;
    const int t = lane & 3;

    const uint32_t laneA = (uint32_t)((lane & 15) * ASTR + (lane >> 4) * 16);
    const uint32_t laneB = (uint32_t)(((lane & 7) + ((lane >> 4) & 1) * 8) * ASTR +
                                      ((lane >> 3) & 1) * 16);

    int acc0[2][2][4], acc1[2][2][4], acc2[2][2][4], acc3[2][2][4];
#pragma unroll
    for (int i = 0; i < 2; i++)
#pragma unroll
        for (int j = 0; j < 2; j++)
#pragma unroll
            for (int q = 0; q < 4; q++) {
                acc0[i][j][q] = 0; acc1[i][j][q] = 0; acc2[i][j][q] = 0; acc3[i][j][q] = 0;
            }

    // raw-A cp mapping (self-mapped: converter reads exactly what it wrote)
    const int arow = tid >> 2, aq = tid & 3;
    const float* Asrc = x + (size_t)(m0 + arow) * D_DIM + aq * 8;
    const uint32_t aRawD = (uint32_t)(arow * RAW_STR + aq * 32);
    // B limb cp mapping: 512 units = 64 rows x 4 planes x 2 halves
    const int bpl = tid >> 7, brow = (tid & 127) >> 1, bhf = tid & 1;
    const int8_t* Bsrc = &g_Wq[bpl][(size_t)(n0 + brow) * D_DIM + bhf * 16];
    const uint32_t bDst = (uint32_t)(brow * ASTR + bhf * 16);

    auto cpRaw = [&](int st, int c) {
        const float* s = Asrc + c * BK;
        uint32_t d = sb + RAW_L(st) + aRawD;
        cpasync16(d, s);
        cpasync16(d + 16, s + 4);
    };
    auto cpB = [&](int st, int c) {
        cpasync16(sb + B_L(st, bpl) + bDst, Bsrc + c * BK);
    };
    // convert own raw rows (stage rawst) -> A limb planes (stage st)
    auto convertA = [&](int st, int rawst) {
        const char* rp = smc + RAW_L(rawst) + aRawD;
        float4 v0 = *(const float4*)rp;
        float4 v1 = *(const float4*)(rp + 16);
        uint32_t w0 = packA(v0.x), w1 = packA(v0.y), w2 = packA(v0.z), w3 = packA(v0.w);
        uint32_t w4 = packA(v1.x), w5 = packA(v1.y), w6 = packA(v1.z), w7 = packA(v1.w);
        const uint32_t dofs = (uint32_t)(arow * ASTR + aq * 8);
#pragma unroll
        for (int p = 0; p < 4; p++) {
            const uint32_t sel = (uint32_t)(3 - p) * 0x11u + 0x40u;
            uint32_t lo = __byte_perm(w0, w1, sel), hi = __byte_perm(w2, w3, sel);
            uint32_t o0 = __byte_perm(lo, hi, 0x5410);
            lo = __byte_perm(w4, w5, sel); hi = __byte_perm(w6, w7, sel);
            uint32_t o1 = __byte_perm(lo, hi, 0x5410);
            *(uint2*)(smc + A_L(st, p) + dofs) = make_uint2(o0, o1);
        }
    };

    // ---- prologue ----
    cpB(0, 0);      CP_COMMIT();          // group: B(0)
    cpRaw(0, 0);    CP_COMMIT();          // group: rawA(0)
    cpRaw(1, 1);    CP_COMMIT();          // group: rawA(1)
    CP_WAIT(1);                            // B(0), rawA(0) done
    convertA(0, 0);
    __syncthreads();

    for (int c = 0; c < NCHUNK; c++) {
        const int cur = c & 1, nxt = cur ^ 1;
        // prefetch: B(c+1) then rawA(c+2)  (commit order matters for waits)
        if (c + 1 < NCHUNK) cpB(nxt, c + 1);
        CP_COMMIT();
        if (c + 2 < NCHUNK) cpRaw(cur, c + 2);
        CP_COMMIT();
        CP_WAIT(2);                        // rawA(c+1) own-copies visible

        const uint32_t aB = sb + (uint32_t)(wm * ASTR) + laneA;
        const uint32_t bB = sb + (uint32_t)(wn * ASTR) + laneB;

        uint32_t A0[2][4], A1[2][4], Ax[2][4];
        uint32_t B0f[2][2], B1f[2][2], Bxf[2][2];

        // --- part 1: buckets using A0/A1, B0/B1 ---
        ldsm4(B0f[0][0], B0f[0][1], B0f[1][0], B0f[1][1], bB + B_L(cur, 0));
        ldsm4(A0[0][0], A0[0][1], A0[0][2], A0[0][3], aB + A_L(cur, 0));
        ldsm4(A0[1][0], A0[1][1], A0[1][2], A0[1][3], aB + A_L(cur, 0) + 16 * ASTR);
#pragma unroll
        for (int mt = 0; mt < 2; mt++)
#pragma unroll
            for (int nt = 0; nt < 2; nt++) imma(acc0[mt][nt], A0[mt], B0f[nt]);
        ldsm4(B1f[0][0], B1f[0][1], B1f[1][0], B1f[1][1], bB + B_L(cur, 1));
#pragma unroll
        for (int mt = 0; mt < 2; mt++)
#pragma unroll
            for (int nt = 0; nt < 2; nt++) imma(acc1[mt][nt], A0[mt], B1f[nt]);
        ldsm4(A1[0][0], A1[0][1], A1[0][2], A1[0][3], aB + A_L(cur, 1));
        ldsm4(A1[1][0], A1[1][1], A1[1][2], A1[1][3], aB + A_L(cur, 1) + 16 * ASTR);
#pragma unroll
        for (int mt = 0; mt < 2; mt++)
#pragma unroll
            for (int nt = 0; nt < 2; nt++) imma(acc1[mt][nt], A1[mt], B0f[nt]);
#pragma unroll
        for (int mt = 0; mt < 2; mt++)
#pragma unroll
            for (int nt = 0; nt < 2; nt++) imma(acc2[mt][nt], A1[mt], B1f[nt]);

        // --- conversion of rawA(c+1) hidden between MMA halves ---
        if (c + 1 < NCHUNK) convertA(nxt, nxt);

        // --- part 2: remaining pairs ---
        ldsm4(Bxf[0][0], Bxf[0][1], Bxf[1][0], Bxf[1][1], bB + B_L(cur, 2));   // B2
#pragma unroll
        for (int mt = 0; mt < 2; mt++)
#pragma unroll
            for (int nt = 0; nt < 2; nt++) imma(acc2[mt][nt], A0[mt], Bxf[nt]);
#pragma unroll
        for (int mt = 0; mt < 2; mt++)
#pragma unroll
            for (int nt = 0; nt < 2; nt++) imma(acc3[mt][nt], A1[mt], Bxf[nt]);
        ldsm4(Ax[0][0], Ax[0][1], Ax[0][2], Ax[0][3], aB + A_L(cur, 2));       // A2
        ldsm4(Ax[1][0], Ax[1][1], Ax[1][2], Ax[1][3], aB + A_L(cur, 2) + 16 * ASTR);
#pragma unroll
        for (int mt = 0; mt < 2; mt++)
#pragma unroll
            for (int nt = 0; nt < 2; nt++) imma(acc2[mt][nt], Ax[mt], B0f[nt]);
#pragma unroll
        for (int mt = 0; mt < 2; mt++)
#pragma unroll
            for (int nt = 0; nt < 2; nt++) imma(acc3[mt][nt], Ax[mt], B1f[nt]);
        ldsm4(Bxf[0][0], Bxf[0][1], Bxf[1][0], Bxf[1][1], bB + B_L(cur, 3));   // B3
#pragma unroll
        for (int mt = 0; mt < 2; mt++)
#pragma unroll
            for (int nt = 0; nt < 2; nt++) imma(acc3[mt][nt], A0[mt], Bxf[nt]);
        ldsm4(Ax[0][0], Ax[0][1], Ax[0][2], Ax[0][3], aB + A_L(cur, 3));       // A3
        ldsm4(Ax[1][0], Ax[1][1], Ax[1][2], Ax[1][3], aB + A_L(cur, 3) + 16 * ASTR);
#pragma unroll
        for (int mt = 0; mt < 2; mt++)
#pragma unroll
            for (int nt = 0; nt < 2; nt++) imma(acc3[mt][nt], Ax[mt], B0f[nt]);

        CP_WAIT(1);                        // B(c+1) landed
        __syncthreads();
    }

    // ---- epilogue: recombine buckets, sigmoid, store ----
#pragma unroll
    for (int mt = 0; mt < 2; mt++) {
        const int r0 = m0 + wm + mt * 16 + g;
#pragma unroll
        for (int nt = 0; nt < 2; nt++) {
            const int cc = n0 + wn + nt * 8 + 2 * t;
            float z[4];
#pragma unroll
            for (int q = 0; q < 4; q++) {
                float v = fmaf((float)acc3[mt][nt][q], C3,
                         fmaf((float)acc2[mt][nt][q], C2,
                         fmaf((float)acc1[mt][nt][q], C1,
                              (float)acc0[mt][nt][q] * C0)));
                z[q] = 1.0f / (1.0f + expf(-v));
            }
            *(float2*)(g_scores + (size_t)r0 * E_EXP + cc) = make_float2(z[0], z[1]);
            *(float2*)(g_scores + (size_t)(r0 + 8) * E_EXP + cc) = make_float2(z[2], z[3]);
        }
    }
}

// ---------------------------------------------------------------------------
// Routing: one block per token; warp == group. jax top_k tie semantics.
// ---------------------------------------------------------------------------
__global__ __launch_bounds__(256) void route_kernel(
    const float* __restrict__ bias, float* __restrict__ out, int write_indices) {
    const int tok = blockIdx.x;
    const int e = threadIdx.x;
    const int lane = e & 31;
    const int warp = e >> 5;

    __shared__ float gsc[N_GROUPS];
    __shared__ unsigned keepmask;
    __shared__ float wv[N_GROUPS];
    __shared__ int wi[N_GROUPS];
    __shared__ int sel_idx[TOP_K];
    __shared__ int sel_warp;
    __shared__ float selw[TOP_K];

    const float score = g_scores[(size_t)tok * E_EXP + e];
    const float s = score + bias[e];

    {
        float v = s; int i = lane;
#pragma unroll
        for (int off = 16; off; off >>= 1) {
            float ov = __shfl_xor_sync(0xffffffffu, v, off);
            int oi = __shfl_xor_sync(0xffffffffu, i, off);
            if (ov > v || (ov == v && oi < i)) { v = ov; i = oi; }
        }
        float m1 = v;
        float v2 = (lane == i) ? -FLT_MAX : s;
#pragma unroll
        for (int off = 16; off; off >>= 1) v2 = fmaxf(v2, __shfl_xor_sync(0xffffffffu, v2, off));
        if (lane == 0) gsc[warp] = m1 + v2;
    }
    __syncthreads();

    if (e == 0) {
        unsigned m = 0;
#pragma unroll
        for (int it = 0; it < TOPK_GROUPS; it++) {
            int best = -1; float bv = -FLT_MAX;
#pragma unroll
            for (int gg = 0; gg < N_GROUPS; gg++)
                if (!((m >> gg) & 1u) && gsc[gg] > bv) { bv = gsc[gg]; best = gg; }
            m |= (1u << best);
        }
        keepmask = m;
    }
    __syncthreads();

    float cur = ((keepmask >> warp) & 1u) ? s : 0.0f;

    auto warp_best = [&](float v) {
        int i = e;
#pragma unroll
        for (int off = 16; off; off >>= 1) {
            float ov = __shfl_xor_sync(0xffffffffu, v, off);
            int oi = __shfl_xor_sync(0xffffffffu, i, off);
            if (ov > v || (ov == v && oi < i)) { v = ov; i = oi; }
        }
        if (lane == 0) { wv[warp] = v; wi[warp] = i; }
    };

    warp_best(cur);
    __syncthreads();

    for (int k = 0; k < TOP_K; k++) {
        if (e == 0) {
            int b = 0;
#pragma unroll
            for (int gg = 1; gg < N_GROUPS; gg++)
                if (wv[gg] > wv[b] || (wv[gg] == wv[b] && wi[gg] < wi[b])) b = gg;
            sel_idx[k] = wi[b];
            sel_warp = b;
        }
        __syncthreads();
        int sw = sel_warp;
        if (warp == sw) {
            if (e == sel_idx[k]) cur = -FLT_MAX;
            warp_best(cur);
        }
        __syncthreads();
    }

    if (e < TOP_K) selw[e] = g_scores[(size_t)tok * E_EXP + sel_idx[e]];
    __syncthreads();
    if (e == 0) {
        float sum = 0.0f;
#pragma unroll
        for (int k = 0; k < TOP_K; k++) sum += selw[k];
        float scale = 2.5f / (sum + 1e-20f);
#pragma unroll
        for (int k = 0; k < TOP_K; k++) {
            out[(size_t)tok * TOP_K + k] = selw[k] * scale;
            if (write_indices)
                out[(size_t)T_TOK * TOP_K + (size_t)tok * TOP_K + k] = (float)sel_idx[k];
        }
    }
}

// ---------------------------------------------------------------------------
extern "C" void kernel_launch(void* const* d_in, const int* in_sizes, int n_in,
                              void* d_out, int out_size) {
    const float* x = (const float*)d_in[0];
    const float* W = (const float*)d_in[1];
    const float* bias = (const float*)d_in[2];
    float* out = (float*)d_out;

    cudaFuncSetAttribute(gemm_imma_kernel,
                         cudaFuncAttributeMaxDynamicSharedMemorySize, SMEM_BYTES);

    wsplit_kernel<<<dim3(D_DIM / 32, E_EXP / 32), dim3(32, 8)>>>(W);
    gemm_imma_kernel<<<dim3(E_EXP / BN, T_TOK / BM), NTHREADS, SMEM_BYTES>>>(x);

    int write_indices = (out_size >= 2 * T_TOK * TOP_K) ? 1 : 0;
    route_kernel<<<T_TOK, 256>>>(bias, out, write_indices);
}

// round 14
// speedup vs baseline: 4.1849x; 4.1849x over previous
#include <cuda_runtime.h>
#include <cuda_fp16.h>
#include <float.h>
#include <math.h>
#include <stdint.h>

// ---------------- problem constants ----------------
#define T_TOK 8192
#define D_DIM 7168
#define E_EXP 256
#define N_GROUPS 8
#define TOPK_GROUPS 4
#define TOP_K 8

// ---------------- GEMM tiling ----------------
#define BM 128
#define BN 64
#define BK 32
#define NCHUNK (D_DIM / BK)      // 224
#define NTHREADS 512

// smem rows: 40 halves = 80 bytes (16B-aligned rows; ldmatrix conflict-free)
#define ROW_B 80
#define A_SP_BYTES (128 * ROW_B)                 // 10240
#define B_SP_BYTES (64 * ROW_B)                  // 5120
#define A_OFF(st, sp) (((st) * 2 + (sp)) * A_SP_BYTES)
#define B_BASE (2 * 2 * A_SP_BYTES)              // 40960
#define B_OFF(st, sp) (B_BASE + ((st) * 2 + (sp)) * B_SP_BYTES)
#define SMEM_BYTES (B_BASE + 2 * 2 * B_SP_BYTES) // 61440

// piece scales: v ~= vh + vm*2^-11 (+ dropped 2^-22 residual)
#define SC_UP1   2048.0f           // 2^11
#define SC_DN1   4.8828125e-4f     // 2^-11

// ---------------- device scratch ----------------
__device__ float g_scores[(size_t)T_TOK * E_EXP];     // sigmoid scores [T][E]
__device__ __half g_Bh[(size_t)E_EXP * D_DIM];        // W^T piece hi   [E][D]
__device__ __half g_Bm[(size_t)E_EXP * D_DIM];        // W^T piece mid (x 2^11)

// ---------------- PTX helpers ----------------
__device__ __forceinline__ uint32_t smem_u32(const void* p) {
    uint32_t a;
    asm("{ .reg .u64 t; cvta.to.shared.u64 t, %1; cvt.u32.u64 %0, t; }" : "=r"(a) : "l"(p));
    return a;
}
__device__ __forceinline__ void mma16816(float* c, const uint32_t* a, const uint32_t* b) {
    asm volatile(
        "mma.sync.aligned.m16n8k16.row.col.f32.f16.f16.f32 "
        "{%0,%1,%2,%3}, {%4,%5,%6,%7}, {%8,%9}, {%0,%1,%2,%3};"
        : "+f"(c[0]), "+f"(c[1]), "+f"(c[2]), "+f"(c[3])
        : "r"(a[0]), "r"(a[1]), "r"(a[2]), "r"(a[3]), "r"(b[0]), "r"(b[1]));
}
__device__ __forceinline__ void ldsm4(uint32_t& r0, uint32_t& r1, uint32_t& r2, uint32_t& r3,
                                      uint32_t addr) {
    asm volatile("ldmatrix.sync.aligned.m8n8.x4.shared.b16 {%0,%1,%2,%3}, [%4];"
                 : "=r"(r0), "=r"(r1), "=r"(r2), "=r"(r3) : "r"(addr));
}
__device__ __forceinline__ void cpasync16(uint32_t saddr, const void* g) {
    asm volatile("cp.async.cg.shared.global [%0], [%1], 16;" :: "r"(saddr), "l"(g));
}
#define CP_COMMIT() asm volatile("cp.async.commit_group;" ::: "memory")
#define CP_WAIT0()  asm volatile("cp.async.wait_group 0;" ::: "memory")

// 2-way split of two floats -> two packed fp16 pairs (elem0 in low 16 bits)
__device__ __forceinline__ void split2_2(float fx, float fy, uint32_t& h, uint32_t& m) {
    __half hx = __float2half_rn(fx), hy = __float2half_rn(fy);
    float rx = fx - __half2float(hx), ry = fy - __half2float(hy);
    __half mx = __float2half_rn(rx * SC_UP1), my = __float2half_rn(ry * SC_UP1);
    h = ((uint32_t)__half_as_ushort(hy) << 16) | (uint32_t)__half_as_ushort(hx);
    m = ((uint32_t)__half_as_ushort(my) << 16) | (uint32_t)__half_as_ushort(mx);
}

// ---------------------------------------------------------------------------
// W split + transpose: W[k][e] f32 -> g_Bh/g_Bm [e][k]
// ---------------------------------------------------------------------------
__global__ __launch_bounds__(256) void wsplit_kernel(const float* __restrict__ W) {
    __shared__ float tile[32][33];
    const int k0 = blockIdx.x * 32, e0 = blockIdx.y * 32;
    const int tx = threadIdx.x, ty = threadIdx.y;   // 32 x 8
#pragma unroll
    for (int i = 0; i < 4; i++)
        tile[ty + 8 * i][tx] = W[(size_t)(k0 + ty + 8 * i) * E_EXP + e0 + tx];
    __syncthreads();
#pragma unroll
    for (int i = 0; i < 4; i++) {
        const int e = e0 + ty + 8 * i;
        const int k = k0 + tx;
        float f = tile[tx][ty + 8 * i];
        __half h = __float2half_rn(f);
        float r1 = f - __half2float(h);
        __half m = __float2half_rn(r1 * SC_UP1);
        size_t o = (size_t)e * D_DIM + k;
        g_Bh[o] = h;
        g_Bm[o] = m;
    }
}

// ---------------------------------------------------------------------------
// GEMM: scores = sigmoid(x @ W), fp16x2-split mma.sync, 4 terms
// (hh + (hm+mh)*2^-11 + mm*2^-22; 2^-22-order cross terms dropped).
// Grid (4, 64) = 256 CTAs. CTA 128x64, 512 threads, 16 warps 4(M)x4(N),
// warp tile 32x16.
// ---------------------------------------------------------------------------
__global__ __launch_bounds__(NTHREADS, 1) void gemm_hmma4_kernel(const float* __restrict__ x) {
    extern __shared__ char smc[];
    const uint32_t sb = smem_u32(smc);

    const int tid = threadIdx.x;
    const int lane = tid & 31, wid = tid >> 5;
    const int m0 = blockIdx.y * BM;
    const int n0 = blockIdx.x * BN;
    const int wm = (wid & 3) * 32;     // warp M offset
    const int wn = (wid >> 2) * 16;    // warp N offset
    const int g = lane >> 2;
    const int t = lane & 3;

    // ldmatrix per-lane offsets (bytes)
    const uint32_t laneA = (uint32_t)((lane & 15) * ROW_B + (lane >> 4) * 16);
    const uint32_t laneB = (uint32_t)(((lane & 7) + ((lane >> 4) & 1) * 8) * ROW_B +
                                      ((lane >> 3) & 1) * 16);

    float acc0[2][2][4], acc1[2][2][4], acc2[2][2][4];
#pragma unroll
    for (int i = 0; i < 2; i++)
#pragma unroll
        for (int j = 0; j < 2; j++)
#pragma unroll
            for (int q = 0; q < 4; q++) {
                acc0[i][j][q] = 0.0f; acc1[i][j][q] = 0.0f; acc2[i][j][q] = 0.0f;
            }

    // ---- global load mappings ----
    // A: 512 threads, row = tid>>2 (0..127), 8 floats at akoff = (tid&3)*8
    const int arow = tid >> 2;
    const int akoff = (tid & 3) * 8;
    const float* Ap = x + (size_t)(m0 + arow) * D_DIM + akoff;
    const uint32_t aDst = (uint32_t)(arow * ROW_B + akoff * 2);
    // B: threads 0..255 load, row = tid>>2 (0..63), 16B unit at bq halves
    const int brow = tid >> 2;
    const int bq = (tid & 3) * 8;
    const __half* Bp[2] = {
        g_Bh + (size_t)(n0 + brow) * D_DIM + bq,
        g_Bm + (size_t)(n0 + brow) * D_DIM + bq };
    const uint32_t bDst = (uint32_t)(brow * ROW_B + (tid & 3) * 16);
    const bool bLoader = (tid < 256);

    // ---- helper: split A registers (8 floats) to smem stage ----
    auto stsA = [&](int st, const float* src) {
#pragma unroll
        for (int j = 0; j < 2; j++) {
            float4 v = ((const float4*)src)[j];
            uint32_t h0, mm0, h1, mm1;
            split2_2(v.x, v.y, h0, mm0);
            split2_2(v.z, v.w, h1, mm1);
            const uint32_t o = aDst + 8 * j;
            *(uint2*)(smc + A_OFF(st, 0) + o) = make_uint2(h0, h1);
            *(uint2*)(smc + A_OFF(st, 1) + o) = make_uint2(mm0, mm1);
        }
    };

    // ---- prologue: chunk 0 into stage 0 ----
    {
        if (bLoader) {
#pragma unroll
            for (int sp = 0; sp < 2; sp++) cpasync16(sb + B_OFF(0, sp) + bDst, Bp[sp]);
        }
        CP_COMMIT();
        float a0[8];
#pragma unroll
        for (int j = 0; j < 2; j++) ((float4*)a0)[j] = ((const float4*)Ap)[j];
        stsA(0, a0);
        CP_WAIT0();
    }
    __syncthreads();

    float a_stage[8];

    for (int c = 0; c < NCHUNK; c++) {
        const int cur = c & 1, nxt = cur ^ 1;
        const bool has_next = (c + 1 < NCHUNK);
        if (has_next) {
            const int kn = (c + 1) * BK;
            if (bLoader) {
#pragma unroll
                for (int sp = 0; sp < 2; sp++) cpasync16(sb + B_OFF(nxt, sp) + bDst, Bp[sp] + kn);
            }
            CP_COMMIT();
            const float4* ap4 = (const float4*)(Ap + kn);
#pragma unroll
            for (int j = 0; j < 2; j++) ((float4*)a_stage)[j] = ap4[j];
        }

        // ---- compute: 2 k16 steps from stage `cur` ----
#pragma unroll
        for (int ks = 0; ks < 2; ks++) {
            const uint32_t ko = (uint32_t)(ks * 32);
            const uint32_t aBase = sb + (uint32_t)(wm * ROW_B) + ko + laneA;
            const uint32_t bBase = sb + (uint32_t)(wn * ROW_B) + ko + laneB;

            uint32_t Ah[2][4], Am[2][4];
            uint32_t Bh[2][2], Bm[2][2];

            // hh
            ldsm4(Ah[0][0], Ah[0][1], Ah[0][2], Ah[0][3], aBase + A_OFF(cur, 0));
            ldsm4(Ah[1][0], Ah[1][1], Ah[1][2], Ah[1][3], aBase + A_OFF(cur, 0) + 16 * ROW_B);
            ldsm4(Bh[0][0], Bh[0][1], Bh[1][0], Bh[1][1], bBase + B_OFF(cur, 0));
#pragma unroll
            for (int mt = 0; mt < 2; mt++)
#pragma unroll
                for (int nt = 0; nt < 2; nt++) mma16816(acc0[mt][nt], Ah[mt], Bh[nt]);

            // hm
            ldsm4(Bm[0][0], Bm[0][1], Bm[1][0], Bm[1][1], bBase + B_OFF(cur, 1));
#pragma unroll
            for (int mt = 0; mt < 2; mt++)
#pragma unroll
                for (int nt = 0; nt < 2; nt++) mma16816(acc1[mt][nt], Ah[mt], Bm[nt]);

            // mh, mm
            ldsm4(Am[0][0], Am[0][1], Am[0][2], Am[0][3], aBase + A_OFF(cur, 1));
            ldsm4(Am[1][0], Am[1][1], Am[1][2], Am[1][3], aBase + A_OFF(cur, 1) + 16 * ROW_B);
#pragma unroll
            for (int mt = 0; mt < 2; mt++)
#pragma unroll
                for (int nt = 0; nt < 2; nt++) mma16816(acc1[mt][nt], Am[mt], Bh[nt]);
#pragma unroll
            for (int mt = 0; mt < 2; mt++)
#pragma unroll
                for (int nt = 0; nt < 2; nt++) mma16816(acc2[mt][nt], Am[mt], Bm[nt]);
        }

        if (has_next) {
            stsA(nxt, a_stage);
            CP_WAIT0();
        }
        __syncthreads();
    }

    // ---- epilogue: recombine scales, sigmoid, store ----
#pragma unroll
    for (int mt = 0; mt < 2; mt++) {
        const int r0 = m0 + wm + mt * 16 + g;
#pragma unroll
        for (int nt = 0; nt < 2; nt++) {
            const int cc = n0 + wn + nt * 8 + 2 * t;
            float z0 = acc0[mt][nt][0] + (acc1[mt][nt][0] + acc2[mt][nt][0] * SC_DN1) * SC_DN1;
            float z1 = acc0[mt][nt][1] + (acc1[mt][nt][1] + acc2[mt][nt][1] * SC_DN1) * SC_DN1;
            float z2 = acc0[mt][nt][2] + (acc1[mt][nt][2] + acc2[mt][nt][2] * SC_DN1) * SC_DN1;
            float z3 = acc0[mt][nt][3] + (acc1[mt][nt][3] + acc2[mt][nt][3] * SC_DN1) * SC_DN1;
            float2 v0, v1;
            v0.x = 1.0f / (1.0f + expf(-z0));
            v0.y = 1.0f / (1.0f + expf(-z1));
            v1.x = 1.0f / (1.0f + expf(-z2));
            v1.y = 1.0f / (1.0f + expf(-z3));
            *(float2*)(g_scores + (size_t)r0 * E_EXP + cc) = v0;
            *(float2*)(g_scores + (size_t)(r0 + 8) * E_EXP + cc) = v1;
        }
    }
}

// ---------------------------------------------------------------------------
// Routing: one block per token; warp == group. jax top_k tie semantics.
// ---------------------------------------------------------------------------
__global__ __launch_bounds__(256) void route_kernel(
    const float* __restrict__ bias, float* __restrict__ out, int write_indices) {
    const int tok = blockIdx.x;
    const int e = threadIdx.x;
    const int lane = e & 31;
    const int warp = e >> 5;

    __shared__ float gsc[N_GROUPS];
    __shared__ unsigned keepmask;
    __shared__ float wv[N_GROUPS];
    __shared__ int wi[N_GROUPS];
    __shared__ int sel_idx[TOP_K];
    __shared__ int sel_warp;
    __shared__ float selw[TOP_K];

    const float score = g_scores[(size_t)tok * E_EXP + e];
    const float s = score + bias[e];

    {
        float v = s; int i = lane;
#pragma unroll
        for (int off = 16; off; off >>= 1) {
            float ov = __shfl_xor_sync(0xffffffffu, v, off);
            int oi = __shfl_xor_sync(0xffffffffu, i, off);
            if (ov > v || (ov == v && oi < i)) { v = ov; i = oi; }
        }
        float m1 = v;
        float v2 = (lane == i) ? -FLT_MAX : s;
#pragma unroll
        for (int off = 16; off; off >>= 1) v2 = fmaxf(v2, __shfl_xor_sync(0xffffffffu, v2, off));
        if (lane == 0) gsc[warp] = m1 + v2;
    }
    __syncthreads();

    if (e == 0) {
        unsigned m = 0;
#pragma unroll
        for (int it = 0; it < TOPK_GROUPS; it++) {
            int best = -1; float bv = -FLT_MAX;
#pragma unroll
            for (int gg = 0; gg < N_GROUPS; gg++)
                if (!((m >> gg) & 1u) && gsc[gg] > bv) { bv = gsc[gg]; best = gg; }
            m |= (1u << best);
        }
        keepmask = m;
    }
    __syncthreads();

    float cur = ((keepmask >> warp) & 1u) ? s : 0.0f;

    auto warp_best = [&](float v) {
        int i = e;
#pragma unroll
        for (int off = 16; off; off >>= 1) {
            float ov = __shfl_xor_sync(0xffffffffu, v, off);
            int oi = __shfl_xor_sync(0xffffffffu, i, off);
            if (ov > v || (ov == v && oi < i)) { v = ov; i = oi; }
        }
        if (lane == 0) { wv[warp] = v; wi[warp] = i; }
    };

    warp_best(cur);
    __syncthreads();

    for (int k = 0; k < TOP_K; k++) {
        if (e == 0) {
            int b = 0;
#pragma unroll
            for (int gg = 1; gg < N_GROUPS; gg++)
                if (wv[gg] > wv[b] || (wv[gg] == wv[b] && wi[gg] < wi[b])) b = gg;
            sel_idx[k] = wi[b];
            sel_warp = b;
        }
        __syncthreads();
        int sw = sel_warp;
        if (warp == sw) {
            if (e == sel_idx[k]) cur = -FLT_MAX;
            warp_best(cur);
        }
        __syncthreads();
    }

    if (e < TOP_K) selw[e] = g_scores[(size_t)tok * E_EXP + sel_idx[e]];
    __syncthreads();
    if (e == 0) {
        float sum = 0.0f;
#pragma unroll
        for (int k = 0; k < TOP_K; k++) sum += selw[k];
        float scale = 2.5f / (sum + 1e-20f);
#pragma unroll
        for (int k = 0; k < TOP_K; k++) {
            out[(size_t)tok * TOP_K + k] = selw[k] * scale;
            if (write_indices)
                out[(size_t)T_TOK * TOP_K + (size_t)tok * TOP_K + k] = (float)sel_idx[k];
        }
    }
}

// ---------------------------------------------------------------------------
extern "C" void kernel_launch(void* const* d_in, const int* in_sizes, int n_in,
                              void* d_out, int out_size) {
    const float* x = (const float*)d_in[0];
    const float* W = (const float*)d_in[1];
    const float* bias = (const float*)d_in[2];
    float* out = (float*)d_out;

    cudaFuncSetAttribute(gemm_hmma4_kernel,
                         cudaFuncAttributeMaxDynamicSharedMemorySize, SMEM_BYTES);

    wsplit_kernel<<<dim3(D_DIM / 32, E_EXP / 32), dim3(32, 8)>>>(W);
    gemm_hmma4_kernel<<<dim3(E_EXP / BN, T_TOK / BM), NTHREADS, SMEM_BYTES>>>(x);

    int write_indices = (out_size >= 2 * T_TOK * TOP_K) ? 1 : 0;
    route_kernel<<<T_TOK, 256>>>(bias, out, write_indices);
}

// round 15
// speedup vs baseline: 4.9014x; 1.1712x over previous
#include <cuda_runtime.h>
#include <cuda_fp16.h>
#include <float.h>
#include <math.h>
#include <stdint.h>

// ---------------- problem constants ----------------
#define T_TOK 8192
#define D_DIM 7168
#define E_EXP 256
#define N_GROUPS 8
#define TOPK_GROUPS 4
#define TOP_K 8

// ---------------- GEMM tiling ----------------
#define BM 128
#define BN 64
#define BK 32
#define NCHUNK (D_DIM / BK)      // 224
#define NTHREADS 512

// smem rows: 40 halves = 80 bytes (16B-aligned rows; ldmatrix conflict-free)
#define ROW_B 80
#define A_SP_BYTES (128 * ROW_B)                 // 10240
#define B_SP_BYTES (64 * ROW_B)                  // 5120
#define A_OFF(st, sp) (((st) * 2 + (sp)) * A_SP_BYTES)
#define B_BASE (2 * 2 * A_SP_BYTES)              // 40960
#define B_OFF(st, sp) (B_BASE + ((st) * 2 + (sp)) * B_SP_BYTES)
#define SMEM_BYTES (B_BASE + 2 * 2 * B_SP_BYTES) // 61440

// piece scales: v ~= vh + vm*2^-11 (+ dropped ~2^-24 residual)
#define SC_UP1   2048.0f           // 2^11
#define SC_DN1   4.8828125e-4f     // 2^-11

// ---------------- device scratch ----------------
__device__ float g_scores[(size_t)T_TOK * E_EXP];     // sigmoid scores [T][E]
__device__ __half g_Bh[(size_t)E_EXP * D_DIM];        // W^T piece hi   [E][D]
__device__ __half g_Bm[(size_t)E_EXP * D_DIM];        // W^T piece mid (x 2^11)

// ---------------- PTX helpers ----------------
__device__ __forceinline__ uint32_t smem_u32(const void* p) {
    uint32_t a;
    asm("{ .reg .u64 t; cvta.to.shared.u64 t, %1; cvt.u32.u64 %0, t; }" : "=r"(a) : "l"(p));
    return a;
}
__device__ __forceinline__ void mma16816(float* c, const uint32_t* a, const uint32_t* b) {
    asm volatile(
        "mma.sync.aligned.m16n8k16.row.col.f32.f16.f16.f32 "
        "{%0,%1,%2,%3}, {%4,%5,%6,%7}, {%8,%9}, {%0,%1,%2,%3};"
        : "+f"(c[0]), "+f"(c[1]), "+f"(c[2]), "+f"(c[3])
        : "r"(a[0]), "r"(a[1]), "r"(a[2]), "r"(a[3]), "r"(b[0]), "r"(b[1]));
}
__device__ __forceinline__ void ldsm4(uint32_t& r0, uint32_t& r1, uint32_t& r2, uint32_t& r3,
                                      uint32_t addr) {
    asm volatile("ldmatrix.sync.aligned.m8n8.x4.shared.b16 {%0,%1,%2,%3}, [%4];"
                 : "=r"(r0), "=r"(r1), "=r"(r2), "=r"(r3) : "r"(addr));
}
__device__ __forceinline__ void cpasync16(uint32_t saddr, const void* g) {
    asm volatile("cp.async.cg.shared.global [%0], [%1], 16;" :: "r"(saddr), "l"(g));
}
#define CP_COMMIT() asm volatile("cp.async.commit_group;" ::: "memory")
#define CP_WAIT0()  asm volatile("cp.async.wait_group 0;" ::: "memory")

// 2-way split of two floats -> two packed fp16 pairs (elem0 in low 16 bits)
__device__ __forceinline__ void split2_2(float fx, float fy, uint32_t& h, uint32_t& m) {
    __half hx = __float2half_rn(fx), hy = __float2half_rn(fy);
    float rx = fx - __half2float(hx), ry = fy - __half2float(hy);
    __half mx = __float2half_rn(rx * SC_UP1), my = __float2half_rn(ry * SC_UP1);
    h = ((uint32_t)__half_as_ushort(hy) << 16) | (uint32_t)__half_as_ushort(hx);
    m = ((uint32_t)__half_as_ushort(my) << 16) | (uint32_t)__half_as_ushort(mx);
}

// ---------------------------------------------------------------------------
// W split + transpose: W[k][e] f32 -> g_Bh/g_Bm [e][k]
// ---------------------------------------------------------------------------
__global__ __launch_bounds__(256) void wsplit_kernel(const float* __restrict__ W) {
    __shared__ float tile[32][33];
    const int k0 = blockIdx.x * 32, e0 = blockIdx.y * 32;
    const int tx = threadIdx.x, ty = threadIdx.y;   // 32 x 8
#pragma unroll
    for (int i = 0; i < 4; i++)
        tile[ty + 8 * i][tx] = W[(size_t)(k0 + ty + 8 * i) * E_EXP + e0 + tx];
    __syncthreads();
#pragma unroll
    for (int i = 0; i < 4; i++) {
        const int e = e0 + ty + 8 * i;
        const int k = k0 + tx;
        float f = tile[tx][ty + 8 * i];
        __half h = __float2half_rn(f);
        float r1 = f - __half2float(h);
        __half m = __float2half_rn(r1 * SC_UP1);
        size_t o = (size_t)e * D_DIM + k;
        g_Bh[o] = h;
        g_Bm[o] = m;
    }
}

// ---------------------------------------------------------------------------
// GEMM: scores = sigmoid(x @ W), fp16x2-split mma.sync, 3 terms
// (hh + (hm+mh)*2^-11; ~2^-24-order terms dropped).
// Grid (4, 64) = 256 CTAs. CTA 128x64, 512 threads, 16 warps 4(M)x4(N),
// warp tile 32x16.
// ---------------------------------------------------------------------------
__global__ __launch_bounds__(NTHREADS, 1) void gemm_hmma3t_kernel(const float* __restrict__ x) {
    extern __shared__ char smc[];
    const uint32_t sb = smem_u32(smc);

    const int tid = threadIdx.x;
    const int lane = tid & 31, wid = tid >> 5;
    const int m0 = blockIdx.y * BM;
    const int n0 = blockIdx.x * BN;
    const int wm = (wid & 3) * 32;     // warp M offset
    const int wn = (wid >> 2) * 16;    // warp N offset
    const int g = lane >> 2;
    const int t = lane & 3;

    // ldmatrix per-lane offsets (bytes)
    const uint32_t laneA = (uint32_t)((lane & 15) * ROW_B + (lane >> 4) * 16);
    const uint32_t laneB = (uint32_t)(((lane & 7) + ((lane >> 4) & 1) * 8) * ROW_B +
                                      ((lane >> 3) & 1) * 16);

    float acc0[2][2][4], acc1[2][2][4];
#pragma unroll
    for (int i = 0; i < 2; i++)
#pragma unroll
        for (int j = 0; j < 2; j++)
#pragma unroll
            for (int q = 0; q < 4; q++) { acc0[i][j][q] = 0.0f; acc1[i][j][q] = 0.0f; }

    // ---- global load mappings ----
    // A: 512 threads, row = tid>>2 (0..127), 8 floats at akoff = (tid&3)*8
    const int arow = tid >> 2;
    const int akoff = (tid & 3) * 8;
    const float* Ap = x + (size_t)(m0 + arow) * D_DIM + akoff;
    const uint32_t aDst = (uint32_t)(arow * ROW_B + akoff * 2);
    // B: threads 0..255 load, row = tid>>2 (0..63), 16B unit at bq halves
    const int brow = tid >> 2;
    const int bq = (tid & 3) * 8;
    const __half* Bp[2] = {
        g_Bh + (size_t)(n0 + brow) * D_DIM + bq,
        g_Bm + (size_t)(n0 + brow) * D_DIM + bq };
    const uint32_t bDst = (uint32_t)(brow * ROW_B + (tid & 3) * 16);
    const bool bLoader = (tid < 256);

    // ---- helper: split A registers (8 floats) to smem stage ----
    auto stsA = [&](int st, const float* src) {
#pragma unroll
        for (int j = 0; j < 2; j++) {
            float4 v = ((const float4*)src)[j];
            uint32_t h0, mm0, h1, mm1;
            split2_2(v.x, v.y, h0, mm0);
            split2_2(v.z, v.w, h1, mm1);
            const uint32_t o = aDst + 8 * j;
            *(uint2*)(smc + A_OFF(st, 0) + o) = make_uint2(h0, h1);
            *(uint2*)(smc + A_OFF(st, 1) + o) = make_uint2(mm0, mm1);
        }
    };

    // ---- prologue: chunk 0 into stage 0 ----
    {
        if (bLoader) {
#pragma unroll
            for (int sp = 0; sp < 2; sp++) cpasync16(sb + B_OFF(0, sp) + bDst, Bp[sp]);
        }
        CP_COMMIT();
        float a0[8];
#pragma unroll
        for (int j = 0; j < 2; j++) ((float4*)a0)[j] = ((const float4*)Ap)[j];
        stsA(0, a0);
        CP_WAIT0();
    }
    __syncthreads();

    float a_stage[8];

    for (int c = 0; c < NCHUNK; c++) {
        const int cur = c & 1, nxt = cur ^ 1;
        const bool has_next = (c + 1 < NCHUNK);
        if (has_next) {
            const int kn = (c + 1) * BK;
            if (bLoader) {
#pragma unroll
                for (int sp = 0; sp < 2; sp++) cpasync16(sb + B_OFF(nxt, sp) + bDst, Bp[sp] + kn);
            }
            CP_COMMIT();
            const float4* ap4 = (const float4*)(Ap + kn);
#pragma unroll
            for (int j = 0; j < 2; j++) ((float4*)a_stage)[j] = ap4[j];
        }

        // ---- compute: 2 k16 steps from stage `cur` ----
#pragma unroll
        for (int ks = 0; ks < 2; ks++) {
            const uint32_t ko = (uint32_t)(ks * 32);
            const uint32_t aBase = sb + (uint32_t)(wm * ROW_B) + ko + laneA;
            const uint32_t bBase = sb + (uint32_t)(wn * ROW_B) + ko + laneB;

            uint32_t Ah[2][4], Am[2][4];
            uint32_t Bh[2][2], Bm[2][2];

            // hh
            ldsm4(Ah[0][0], Ah[0][1], Ah[0][2], Ah[0][3], aBase + A_OFF(cur, 0));
            ldsm4(Ah[1][0], Ah[1][1], Ah[1][2], Ah[1][3], aBase + A_OFF(cur, 0) + 16 * ROW_B);
            ldsm4(Bh[0][0], Bh[0][1], Bh[1][0], Bh[1][1], bBase + B_OFF(cur, 0));
#pragma unroll
            for (int mt = 0; mt < 2; mt++)
#pragma unroll
                for (int nt = 0; nt < 2; nt++) mma16816(acc0[mt][nt], Ah[mt], Bh[nt]);

            // hm
            ldsm4(Bm[0][0], Bm[0][1], Bm[1][0], Bm[1][1], bBase + B_OFF(cur, 1));
#pragma unroll
            for (int mt = 0; mt < 2; mt++)
#pragma unroll
                for (int nt = 0; nt < 2; nt++) mma16816(acc1[mt][nt], Ah[mt], Bm[nt]);

            // mh
            ldsm4(Am[0][0], Am[0][1], Am[0][2], Am[0][3], aBase + A_OFF(cur, 1));
            ldsm4(Am[1][0], Am[1][1], Am[1][2], Am[1][3], aBase + A_OFF(cur, 1) + 16 * ROW_B);
#pragma unroll
            for (int mt = 0; mt < 2; mt++)
#pragma unroll
                for (int nt = 0; nt < 2; nt++) mma16816(acc1[mt][nt], Am[mt], Bh[nt]);
        }

        if (has_next) {
            stsA(nxt, a_stage);
            CP_WAIT0();
        }
        __syncthreads();
    }

    // ---- epilogue: recombine scales, sigmoid, store ----
#pragma unroll
    for (int mt = 0; mt < 2; mt++) {
        const int r0 = m0 + wm + mt * 16 + g;
#pragma unroll
        for (int nt = 0; nt < 2; nt++) {
            const int cc = n0 + wn + nt * 8 + 2 * t;
            float z0 = fmaf(acc1[mt][nt][0], SC_DN1, acc0[mt][nt][0]);
            float z1 = fmaf(acc1[mt][nt][1], SC_DN1, acc0[mt][nt][1]);
            float z2 = fmaf(acc1[mt][nt][2], SC_DN1, acc0[mt][nt][2]);
            float z3 = fmaf(acc1[mt][nt][3], SC_DN1, acc0[mt][nt][3]);
            float2 v0, v1;
            v0.x = 1.0f / (1.0f + expf(-z0));
            v0.y = 1.0f / (1.0f + expf(-z1));
            v1.x = 1.0f / (1.0f + expf(-z2));
            v1.y = 1.0f / (1.0f + expf(-z3));
            *(float2*)(g_scores + (size_t)r0 * E_EXP + cc) = v0;
            *(float2*)(g_scores + (size_t)(r0 + 8) * E_EXP + cc) = v1;
        }
    }
}

// ---------------------------------------------------------------------------
// Routing: one block per token; warp == group. jax top_k tie semantics.
// ---------------------------------------------------------------------------
__global__ __launch_bounds__(256) void route_kernel(
    const float* __restrict__ bias, float* __restrict__ out, int write_indices) {
    const int tok = blockIdx.x;
    const int e = threadIdx.x;
    const int lane = e & 31;
    const int warp = e >> 5;

    __shared__ float gsc[N_GROUPS];
    __shared__ unsigned keepmask;
    __shared__ float wv[N_GROUPS];
    __shared__ int wi[N_GROUPS];
    __shared__ int sel_idx[TOP_K];
    __shared__ int sel_warp;
    __shared__ float selw[TOP_K];

    const float score = g_scores[(size_t)tok * E_EXP + e];
    const float s = score + bias[e];

    {
        float v = s; int i = lane;
#pragma unroll
        for (int off = 16; off; off >>= 1) {
            float ov = __shfl_xor_sync(0xffffffffu, v, off);
            int oi = __shfl_xor_sync(0xffffffffu, i, off);
            if (ov > v || (ov == v && oi < i)) { v = ov; i = oi; }
        }
        float m1 = v;
        float v2 = (lane == i) ? -FLT_MAX : s;
#pragma unroll
        for (int off = 16; off; off >>= 1) v2 = fmaxf(v2, __shfl_xor_sync(0xffffffffu, v2, off));
        if (lane == 0) gsc[warp] = m1 + v2;
    }
    __syncthreads();

    if (e == 0) {
        unsigned m = 0;
#pragma unroll
        for (int it = 0; it < TOPK_GROUPS; it++) {
            int best = -1; float bv = -FLT_MAX;
#pragma unroll
            for (int gg = 0; gg < N_GROUPS; gg++)
                if (!((m >> gg) & 1u) && gsc[gg] > bv) { bv = gsc[gg]; best = gg; }
            m |= (1u << best);
        }
        keepmask = m;
    }
    __syncthreads();

    float cur = ((keepmask >> warp) & 1u) ? s : 0.0f;

    auto warp_best = [&](float v) {
        int i = e;
#pragma unroll
        for (int off = 16; off; off >>= 1) {
            float ov = __shfl_xor_sync(0xffffffffu, v, off);
            int oi = __shfl_xor_sync(0xffffffffu, i, off);
            if (ov > v || (ov == v && oi < i)) { v = ov; i = oi; }
        }
        if (lane == 0) { wv[warp] = v; wi[warp] = i; }
    };

    warp_best(cur);
    __syncthreads();

    for (int k = 0; k < TOP_K; k++) {
        if (e == 0) {
            int b = 0;
#pragma unroll
            for (int gg = 1; gg < N_GROUPS; gg++)
                if (wv[gg] > wv[b] || (wv[gg] == wv[b] && wi[gg] < wi[b])) b = gg;
            sel_idx[k] = wi[b];
            sel_warp = b;
        }
        __syncthreads();
        int sw = sel_warp;
        if (warp == sw) {
            if (e == sel_idx[k]) cur = -FLT_MAX;
            warp_best(cur);
        }
        __syncthreads();
    }

    if (e < TOP_K) selw[e] = g_scores[(size_t)tok * E_EXP + sel_idx[e]];
    __syncthreads();
    if (e == 0) {
        float sum = 0.0f;
#pragma unroll
        for (int k = 0; k < TOP_K; k++) sum += selw[k];
        float scale = 2.5f / (sum + 1e-20f);
#pragma unroll
        for (int k = 0; k < TOP_K; k++) {
            out[(size_t)tok * TOP_K + k] = selw[k] * scale;
            if (write_indices)
                out[(size_t)T_TOK * TOP_K + (size_t)tok * TOP_K + k] = (float)sel_idx[k];
        }
    }
}

// ---------------------------------------------------------------------------
extern "C" void kernel_launch(void* const* d_in, const int* in_sizes, int n_in,
                              void* d_out, int out_size) {
    const float* x = (const float*)d_in[0];
    const float* W = (const float*)d_in[1];
    const float* bias = (const float*)d_in[2];
    float* out = (float*)d_out;

    cudaFuncSetAttribute(gemm_hmma3t_kernel,
                         cudaFuncAttributeMaxDynamicSharedMemorySize, SMEM_BYTES);

    wsplit_kernel<<<dim3(D_DIM / 32, E_EXP / 32), dim3(32, 8)>>>(W);
    gemm_hmma3t_kernel<<<dim3(E_EXP / BN, T_TOK / BM), NTHREADS, SMEM_BYTES>>>(x);

    int write_indices = (out_size >= 2 * T_TOK * TOP_K) ? 1 : 0;
    route_kernel<<<T_TOK, 256>>>(bias, out, write_indices);
}